// round 4
// baseline (speedup 1.0000x reference)
#include <cuda_runtime.h>
#include <cuda_bf16.h>
#include <cstdint>

#define BB 32
#define TT 512
#define KK 256

// Packed exp(trans) in bf16: 32 i-blocks x 256 columns, each uint4 = 8 i-values
// (4 packed pairs) for one column j. 128 KB total.
__device__ uint4 g_expT4[(KK / 8) * KK];
__device__ float g_partial[BB];

static __device__ __forceinline__ unsigned int f2bf_rn(float x) {
    // round-to-nearest-even float -> bf16 bits (x is positive finite here)
    unsigned int u = __float_as_uint(x);
    unsigned int r = u + 0x7FFFu + ((u >> 16) & 1u);
    return r >> 16;
}

// ---------------------------------------------------------------------------
// Kernel 1: expT[i][j] = exp(trans[i][j]) -> bf16, packed into the SMEM-friendly
// layout: word w of block (i8, j) holds (bf16 expT[8*i8+2w][j], bf16 expT[8*i8+2w+1][j]).
// ---------------------------------------------------------------------------
__global__ void crf_prep(const float* __restrict__ trans) {
    int idx = blockIdx.x * blockDim.x + threadIdx.x;   // 0 .. 32767
    int i2 = idx >> 8;            // pair index 0..127
    int j  = idx & (KK - 1);
    float e0 = __expf(trans[(2 * i2)     * KK + j]);
    float e1 = __expf(trans[(2 * i2 + 1) * KK + j]);
    unsigned int lo = f2bf_rn(e0);
    unsigned int hi = f2bf_rn(e1);
    int i8 = i2 >> 2;
    int w  = i2 & 3;
    ((unsigned int*)g_expT4)[(i8 * KK + j) * 4 + w] = lo | (hi << 16);
}

// ---------------------------------------------------------------------------
// Kernel 2: one CTA per batch element. 256 threads, thread j owns alpha[j].
// Computes joint score (log_num) and the full forward recursion (log_den).
// ---------------------------------------------------------------------------
__global__ void __launch_bounds__(256, 1) crf_main(
    const float* __restrict__ emissions,
    const int*   __restrict__ tags,
    const int*   __restrict__ mask,     // bool serialized as int32; nonzero = true
    const float* __restrict__ trans)
{
    extern __shared__ unsigned char smraw[];
    uint4* sh_eT  = (uint4*)smraw;                          // 128 KB: packed bf16 expT
    float* sh_ea  = (float*)(smraw + 131072);               // 256 floats: exp(alpha - c)
    float* sh_red = (float*)(smraw + 131072 + 1024);        // 16 floats: reduction scratch

    const int b    = blockIdx.x;
    const int j    = threadIdx.x;
    const int lane = j & 31;
    const int wid  = j >> 5;

    // ---- stage expT into shared memory (L2-hot after first CTA) ----
    for (int idx = j; idx < (KK / 8) * KK; idx += 256)
        sh_eT[idx] = g_expT4[idx];

    // ---- joint (numerator) score: gather emissions at tags + transition scores ----
    float js = 0.0f;
    #pragma unroll
    for (int h = 0; h < 2; ++h) {
        int t = j + h * 256;
        if (mask[b * TT + t] != 0) {
            int tag = tags[b * TT + t];
            js += emissions[((size_t)b * TT + t) * KK + tag];
            if (t >= 1) {
                int tagp = tags[b * TT + t - 1];
                js += trans[tagp * KK + tag];
            }
        }
    }
    #pragma unroll
    for (int s = 16; s; s >>= 1) js += __shfl_xor_sync(0xFFFFFFFFu, js, s);
    if (lane == 0) sh_red[wid] = js;
    __syncthreads();
    if (j == 0) {
        float s = 0.0f;
        #pragma unroll
        for (int w = 0; w < 8; ++w) s += sh_red[w];
        sh_red[8] = s;            // log_num parked in slot 8 (slots 0..7 get reused)
    }
    __syncthreads();

    // ---- forward recursion ----
    const float* em_b = emissions + (size_t)b * TT * KK;
    float alpha = em_b[j];        // alpha0 = emissions[b, 0, :]

    for (int t = 1; t < TT; ++t) {
        // prefetch next emission row + mask (consumed ~1000 cycles later)
        float emit = em_b[t * KK + j];
        int   mv   = mask[b * TT + t];

        // c = max_j alpha[j]
        float m = alpha;
        #pragma unroll
        for (int s = 16; s; s >>= 1) m = fmaxf(m, __shfl_xor_sync(0xFFFFFFFFu, m, s));
        if (lane == 0) sh_red[wid] = m;
        __syncthreads();                          // also fences previous dot-loop reads
        float c = sh_red[0];
        #pragma unroll
        for (int w = 1; w < 8; ++w) c = fmaxf(c, sh_red[w]);

        sh_ea[j] = __expf(alpha - c);             // in (0, 1], underflow -> 0 is fine
        __syncthreads();

        // acc = sum_i exp(alpha_i - c) * expT[i][j]
        float a0 = 0.0f, a1 = 0.0f, a2 = 0.0f, a3 = 0.0f;
        #pragma unroll
        for (int i8 = 0; i8 < 32; ++i8) {
            uint4  p  = sh_eT[i8 * KK + j];                       // 8 bf16 for column j
            float4 e0 = *(const float4*)(sh_ea + i8 * 8);         // broadcast
            float4 e1 = *(const float4*)(sh_ea + i8 * 8 + 4);     // broadcast
            a0 = fmaf(e0.x, __uint_as_float(p.x << 16),          a0);
            a1 = fmaf(e0.y, __uint_as_float(p.x & 0xFFFF0000u),  a1);
            a2 = fmaf(e0.z, __uint_as_float(p.y << 16),          a2);
            a3 = fmaf(e0.w, __uint_as_float(p.y & 0xFFFF0000u),  a3);
            a0 = fmaf(e1.x, __uint_as_float(p.z << 16),          a0);
            a1 = fmaf(e1.y, __uint_as_float(p.z & 0xFFFF0000u),  a1);
            a2 = fmaf(e1.z, __uint_as_float(p.w << 16),          a2);
            a3 = fmaf(e1.w, __uint_as_float(p.w & 0xFFFF0000u),  a3);
        }
        float acc  = (a0 + a1) + (a2 + a3);       // > 0 always (max term ~ expT >= e^-5)
        float anew = c + __logf(acc) + emit;
        alpha = (mv != 0) ? anew : alpha;
    }

    // ---- final logsumexp over alpha ----
    float m = alpha;
    #pragma unroll
    for (int s = 16; s; s >>= 1) m = fmaxf(m, __shfl_xor_sync(0xFFFFFFFFu, m, s));
    if (lane == 0) sh_red[wid] = m;
    __syncthreads();
    float c = sh_red[0];
    #pragma unroll
    for (int w = 1; w < 8; ++w) c = fmaxf(c, sh_red[w]);
    float e = __expf(alpha - c);
    #pragma unroll
    for (int s = 16; s; s >>= 1) e += __shfl_xor_sync(0xFFFFFFFFu, e, s);
    __syncthreads();                              // all reads of sh_red[0..7] done
    if (lane == 0) sh_red[wid] = e;
    __syncthreads();
    if (j == 0) {
        float s = 0.0f;
        #pragma unroll
        for (int w = 0; w < 8; ++w) s += sh_red[w];
        float logden = c + __logf(s);
        g_partial[b] = logden - sh_red[8];        // log_den - log_num
    }
}

// ---------------------------------------------------------------------------
// Kernel 3: deterministic fixed-order mean over batch.
// ---------------------------------------------------------------------------
__global__ void crf_fin(float* __restrict__ out) {
    float s = 0.0f;
    #pragma unroll
    for (int b = 0; b < BB; ++b) s += g_partial[b];
    out[0] = s * (1.0f / (float)BB);
}

extern "C" void kernel_launch(void* const* d_in, const int* in_sizes, int n_in,
                              void* d_out, int out_size) {
    (void)in_sizes; (void)n_in; (void)out_size;
    const float* emissions = (const float*)d_in[0];
    const int*   tags      = (const int*)d_in[1];
    const int*   mask      = (const int*)d_in[2];   // bool -> int32 per harness dtype set
    const float* trans     = (const float*)d_in[3];

    crf_prep<<<128, 256>>>(trans);

    size_t shmem = 131072 + 1024 + 64;
    cudaFuncSetAttribute((const void*)crf_main,
                         cudaFuncAttributeMaxDynamicSharedMemorySize, (int)shmem);
    crf_main<<<BB, 256, shmem>>>(emissions, tags, mask, trans);

    crf_fin<<<1, 1>>>((float*)d_out);
}

// round 5
// speedup vs baseline: 2.4977x; 2.4977x over previous
#include <cuda_runtime.h>
#include <cuda_bf16.h>
#include <cstdint>

#define BB 32
#define TT 512
#define KK 256

// Packed exp(trans) bf16x2 table: word (w, j) = (bf16 expT[2w][j], bf16 expT[2w+1][j]).
// Layout g_expTp[w*KK + j] so per-thread column loads are coalesced.
__device__ unsigned int g_expTp[(KK / 2) * KK];
__device__ float g_partial[BB];

static __device__ __forceinline__ unsigned int f2bf_rn(float x) {
    // round-to-nearest-even float -> bf16 bits (finite, non-NaN inputs here)
    unsigned int u = __float_as_uint(x);
    unsigned int r = u + 0x7FFFu + ((u >> 16) & 1u);
    return r >> 16;
}

#define HFMA2_BF16(d, a, b, c) \
    asm("fma.rn.bf16x2 %0, %1, %2, %3;" : "=r"(d) : "r"(a), "r"(b), "r"(c))

// ---------------------------------------------------------------------------
// Kernel 1: build packed bf16x2 exp(trans) table.
// ---------------------------------------------------------------------------
__global__ void crf_prep(const float* __restrict__ trans) {
    int idx = blockIdx.x * blockDim.x + threadIdx.x;   // 0 .. 32767
    int w = idx >> 8;             // pair index 0..127
    int j = idx & (KK - 1);
    unsigned int lo = f2bf_rn(__expf(trans[(2 * w)     * KK + j]));
    unsigned int hi = f2bf_rn(__expf(trans[(2 * w + 1) * KK + j]));
    g_expTp[w * KK + j] = lo | (hi << 16);
}

// ---------------------------------------------------------------------------
// Kernel 2: one CTA per batch element, 256 threads, thread j owns alpha[j]
// and holds expT[:, j] in 128 bf16x2 registers. One __syncthreads per step.
// Normalizer c is thread 0's alpha lagged by 2 steps (race-free double buffer).
// ---------------------------------------------------------------------------
__global__ void __launch_bounds__(256, 1) crf_main(
    const float* __restrict__ emissions,
    const int*   __restrict__ tags,
    const int*   __restrict__ mask,
    const float* __restrict__ trans)
{
    __shared__ unsigned short sh_eb[2][KK];   // double-buffered exp(alpha-c) in bf16
    __shared__ float sh_c[2];                 // double-buffered lagged normalizer
    __shared__ float sh_red[12];              // reduction scratch (+slot 8 = log_num)

    const int b    = blockIdx.x;
    const int j    = threadIdx.x;
    const int lane = j & 31;
    const int wid  = j >> 5;

    // ---- load expT column j into registers ----
    unsigned int tab[128];
    #pragma unroll
    for (int w = 0; w < 128; ++w)
        tab[w] = g_expTp[w * KK + j];

    // ---- joint (numerator) score ----
    float js = 0.0f;
    #pragma unroll
    for (int h = 0; h < 2; ++h) {
        int t = j + h * 256;
        if (mask[b * TT + t] != 0) {
            int tag = tags[b * TT + t];
            js += emissions[((size_t)b * TT + t) * KK + tag];
            if (t >= 1) {
                int tagp = tags[b * TT + t - 1];
                js += trans[tagp * KK + tag];
            }
        }
    }
    #pragma unroll
    for (int s = 16; s; s >>= 1) js += __shfl_xor_sync(0xFFFFFFFFu, js, s);
    if (lane == 0) sh_red[wid] = js;
    __syncthreads();
    if (j == 0) {
        float s = 0.0f;
        #pragma unroll
        for (int w = 0; w < 8; ++w) s += sh_red[w];
        sh_red[8] = s;                        // park log_num
    }

    // ---- init forward recursion ----
    const float* em_b = emissions + (size_t)b * TT * KK;
    float alpha = em_b[j];                    // alpha0
    if (j == 0) { sh_c[0] = alpha; sh_c[1] = alpha; }
    __syncthreads();

    for (int t = 1; t < TT; ++t) {
        // prefetch (consumed after the dot loop)
        float emit = em_b[t * KK + j];
        int   mv   = mask[b * TT + t];

        const int buf = t & 1;
        // c written at end of step t-2 (or init); ordered by step t-1's sync.
        float c = sh_c[buf];
        sh_eb[buf][j] = (unsigned short)f2bf_rn(__expf(alpha - c));
        __syncthreads();

        // acc = sum_i exp(alpha_i - c) * expT[i][j], bf16x2 groups of 16 i's
        const uint4* eb4 = (const uint4*)sh_eb[buf];
        float acc0 = 0.0f, acc1 = 0.0f;
        #pragma unroll
        for (int g = 0; g < 16; ++g) {
            uint4 e0 = eb4[2 * g];            // e[16g .. 16g+7]   (broadcast)
            uint4 e1 = eb4[2 * g + 1];        // e[16g+8 .. 16g+15]
            unsigned int a2 = 0u;
            HFMA2_BF16(a2, e0.x, tab[8 * g + 0], a2);
            HFMA2_BF16(a2, e0.y, tab[8 * g + 1], a2);
            HFMA2_BF16(a2, e0.z, tab[8 * g + 2], a2);
            HFMA2_BF16(a2, e0.w, tab[8 * g + 3], a2);
            HFMA2_BF16(a2, e1.x, tab[8 * g + 4], a2);
            HFMA2_BF16(a2, e1.y, tab[8 * g + 5], a2);
            HFMA2_BF16(a2, e1.z, tab[8 * g + 6], a2);
            HFMA2_BF16(a2, e1.w, tab[8 * g + 7], a2);
            acc0 += __uint_as_float(a2 << 16);          // low bf16 lane
            acc1 += __uint_as_float(a2 & 0xFFFF0000u);  // high bf16 lane
        }
        float acc  = acc0 + acc1;             // > 0 (largest term ~= 1 * expT)
        float anew = c + __logf(acc) + emit;
        alpha = (mv != 0) ? anew : alpha;

        // publish normalizer for step t+2 (same slot 'buf'); all reads of
        // sh_c[buf] at the top of THIS step happened before this step's sync,
        // and step t+1's sync orders this write before step t+2's reads.
        if (j == 0) sh_c[buf] = alpha;
    }

    // ---- final logsumexp over alpha (exact, fp32) ----
    float m = alpha;
    #pragma unroll
    for (int s = 16; s; s >>= 1) m = fmaxf(m, __shfl_xor_sync(0xFFFFFFFFu, m, s));
    if (lane == 0) sh_red[wid] = m;
    __syncthreads();
    float c = sh_red[0];
    #pragma unroll
    for (int w = 1; w < 8; ++w) c = fmaxf(c, sh_red[w]);
    float e = __expf(alpha - c);
    #pragma unroll
    for (int s = 16; s; s >>= 1) e += __shfl_xor_sync(0xFFFFFFFFu, e, s);
    __syncthreads();                          // reads of sh_red[0..7] done
    if (lane == 0) sh_red[wid] = e;
    __syncthreads();
    if (j == 0) {
        float s = 0.0f;
        #pragma unroll
        for (int w = 0; w < 8; ++w) s += sh_red[w];
        float logden = c + __logf(s);
        g_partial[b] = logden - sh_red[8];    // log_den - log_num
    }
}

// ---------------------------------------------------------------------------
// Kernel 3: deterministic fixed-order mean over batch.
// ---------------------------------------------------------------------------
__global__ void crf_fin(float* __restrict__ out) {
    float s = 0.0f;
    #pragma unroll
    for (int b = 0; b < BB; ++b) s += g_partial[b];
    out[0] = s * (1.0f / (float)BB);
}

extern "C" void kernel_launch(void* const* d_in, const int* in_sizes, int n_in,
                              void* d_out, int out_size) {
    (void)in_sizes; (void)n_in; (void)out_size;
    const float* emissions = (const float*)d_in[0];
    const int*   tags      = (const int*)d_in[1];
    const int*   mask      = (const int*)d_in[2];
    const float* trans     = (const float*)d_in[3];

    crf_prep<<<128, 256>>>(trans);
    crf_main<<<BB, 256>>>(emissions, tags, mask, trans);
    crf_fin<<<1, 1>>>((float*)d_out);
}